// round 15
// baseline (speedup 1.0000x reference)
#include <cuda_runtime.h>
#include <cstdint>

// Problem constants
#define RB      128         // batch  (GEMM N)
#define RROUTE  4608        // routes
#define CCO     160         // C*O    (GEMM M)
#define II      8

// K-split
#define NSPLIT  144         // CTAs
#define CHUNK_R 32          // routes per CTA (K=256)
#define CK_R    4           // routes per chunk
#define KCH     32          // k per chunk
#define NCH     8
#define NTHREADS 512

// smem rows (bytes), padded & 16B aligned, ldmatrix conflict-free
#define A_ROW   80          // W tile row: 40 fp16 (32 used)
#define B_ROW   272         // x tile row: 136 fp16 (128 used)
#define OFF_A   0
#define OFF_B   (CCO * A_ROW)            // 12800
#define BUFB    (OFF_B + KCH * B_ROW)    // 21504 per buffer
#define SMEM_SZ (2 * BUFB)               // 43008 static (double buffered, <48KB)

// partial results, transposed for streaming reduction: [B][NSPLIT][CO]
__device__ float g_partial[RB * NSPLIT * CCO];

// ---------------- helpers ----------------
__device__ __forceinline__ uint32_t smem_u32(const void* p) {
    uint32_t a;
    asm("{ .reg .u64 t; cvta.to.shared.u64 t, %1; cvt.u32.u64 %0, t; }" : "=r"(a) : "l"(p));
    return a;
}
__device__ __forceinline__ uint32_t packh(float e0, float e1) {
    uint32_t d;
    asm("cvt.rn.f16x2.f32 %0, %1, %2;" : "=r"(d) : "f"(e1), "f"(e0));
    return d;
}
// unpack f16x2 -> two f32
__device__ __forceinline__ float2 h2f2(uint32_t h) {
    float2 f;
    asm("{ .reg .f16 l, hi; mov.b32 {l, hi}, %2; cvt.f32.f16 %0, l; cvt.f32.f16 %1, hi; }"
        : "=f"(f.x), "=f"(f.y) : "r"(h));
    return f;
}
__device__ __forceinline__ void sts32(uint32_t a, uint32_t r) {
    asm volatile("st.shared.b32 [%0], %1;" :: "r"(a), "r"(r) : "memory");
}
__device__ __forceinline__ void sts64(uint32_t a, uint32_t r0, uint32_t r1) {
    asm volatile("st.shared.v2.b32 [%0], {%1, %2};" :: "r"(a), "r"(r0), "r"(r1) : "memory");
}
__device__ __forceinline__ void ldmx4(uint32_t* r, uint32_t a) {
    asm volatile("ldmatrix.sync.aligned.m8n8.x4.shared.b16 {%0,%1,%2,%3}, [%4];"
                 : "=r"(r[0]), "=r"(r[1]), "=r"(r[2]), "=r"(r[3]) : "r"(a));
}
__device__ __forceinline__ void ldmx2t(uint32_t* r, uint32_t a) {
    asm volatile("ldmatrix.sync.aligned.m8n8.x2.trans.shared.b16 {%0,%1}, [%2];"
                 : "=r"(r[0]), "=r"(r[1]) : "r"(a));
}
// fp16-accumulator mma: D(f16x2 pair) = A*B + D  — 2x issue rate vs f32 acc
__device__ __forceinline__ void mma16816h(uint32_t* d, const uint32_t* a, const uint32_t* b) {
    asm volatile(
        "mma.sync.aligned.m16n8k16.row.col.f16.f16.f16.f16 "
        "{%0,%1}, {%2,%3,%4,%5}, {%6,%7}, {%0,%1};"
        : "+r"(d[0]), "+r"(d[1])
        : "r"(a[0]), "r"(a[1]), "r"(a[2]), "r"(a[3]), "r"(b[0]), "r"(b[1]));
}
__device__ __forceinline__ float f4elem(const float4& v, int j) {
    switch (j) { case 0: return v.x; case 1: return v.y; case 2: return v.z; default: return v.w; }
}

// ---------------------------------------------------------------------------
// Kernel 1: fp16 mma.sync partial GEMM with fp16 accumulators (2x HMMA rate).
// Two accumulator sets (chunks 0-3 / 4-7, K=128 each) summed in fp32 at the
// epilogue to bound the fp16 running-sum rounding walk.
// 16 warps: 2 (M=co, 80 each) x 8 (N=b, 16 each). Warp tile 80x16 = 5x2 tiles.
// ---------------------------------------------------------------------------
__global__ void __launch_bounds__(NTHREADS, 1)
digitcaps_mma_kernel(const float* __restrict__ x, const float* __restrict__ W)
{
    __shared__ __align__(16) char smem_raw[SMEM_SZ];
    const uint32_t tiles = smem_u32(smem_raw);

    const int tid = threadIdx.x;
    const int lid = tid & 31;
    const int wid = tid >> 5;
    const int wm  = wid & 1;          // M-warp (co)
    const int wn  = wid >> 1;         // N-warp (b)
    const int c0w = wm * 80;
    const int b0w = wn * 16;
    const int r0  = blockIdx.x * CHUNK_R;

    // x conversion task: b-pair bp, quarter q (k = q*4 + j)
    const int bp = tid >> 3;
    const int q  = tid & 7;

    // two fp16x2 accumulator sets: [set][mt][nt][reg]
    uint32_t acc[2][5][2][2];
#pragma unroll
    for (int s = 0; s < 2; s++)
#pragma unroll
        for (int mt = 0; mt < 5; mt++)
#pragma unroll
            for (int nt = 0; nt < 2; nt++) {
                acc[s][mt][nt][0] = 0u;
                acc[s][mt][nt][1] = 0u;
            }

    float4 px0, px1, pw[3];

    auto ldg_chunk = [&](int ck) {
        const int rc0 = r0 + ck * CK_R;
        const float4* xb = (const float4*)(x + ((size_t)(2 * bp) * RROUTE + rc0) * II);
        px0 = __ldg(xb + q);
        px1 = __ldg(xb + (RROUTE * II / 4) + q);     // row b+1
#pragma unroll
        for (int t = 0; t < 3; t++) {
            int idx = tid + t * NTHREADS;
            if (idx < 1280) {
                int rr = idx / 320, rem = idx - rr * 320;
                int co = rem >> 1, ih = rem & 1;
                pw[t] = __ldg((const float4*)(W + ((size_t)(rc0 + rr) * CCO + co) * II) + ih);
            }
        }
    };

    auto sts_chunk = [&](uint32_t bb) {
        // x -> B tile [k][b] (transpose during store; fp16 pair (b, b+1) per word)
#pragma unroll
        for (int j = 0; j < 4; j++) {
            uint32_t h = packh(f4elem(px0, j), f4elem(px1, j));
            sts32(tiles + bb + OFF_B + (uint32_t)((q * 4 + j) * B_ROW + 4 * bp), h);
        }
        // W -> A tile [co][k] (natural, k-contiguous)
#pragma unroll
        for (int t = 0; t < 3; t++) {
            int idx = tid + t * NTHREADS;
            if (idx < 1280) {
                int rr = idx / 320, rem = idx - rr * 320;
                int co = rem >> 1, ih = rem & 1;
                uint32_t h0 = packh(pw[t].x, pw[t].y), h1 = packh(pw[t].z, pw[t].w);
                sts64(tiles + bb + OFF_A + (uint32_t)(co * A_ROW + rr * 16 + ih * 8), h0, h1);
            }
        }
    };

    auto compute = [&](uint32_t bb, int aset) {
#pragma unroll
        for (int ks = 0; ks < 2; ks++) {
            const uint32_t k0 = ks * 16;
            uint32_t bh[2][2];
            const uint32_t brow = k0 + (lid & 7) + ((lid >> 3) & 1) * 8;
#pragma unroll
            for (int nt = 0; nt < 2; nt++)
                ldmx2t(bh[nt], tiles + bb + OFF_B + brow * B_ROW + (uint32_t)(b0w + nt * 8) * 2);
#pragma unroll
            for (int mt = 0; mt < 5; mt++) {
                uint32_t ah[4];
                ldmx4(ah, tiles + bb + OFF_A
                          + (uint32_t)(c0w + mt * 16 + (lid & 15)) * A_ROW
                          + (k0 + (lid >> 4) * 8) * 2);
#pragma unroll
                for (int nt = 0; nt < 2; nt++)
                    mma16816h(acc[aset][mt][nt], ah, bh[nt]);
            }
        }
    };

    // pipeline: prefetch LDG(c+1) in regs over compute(c); STS into idle buffer
    ldg_chunk(0);
    sts_chunk(0);
    __syncthreads();
#pragma unroll 1
    for (int c = 0; c < NCH; c++) {
        const uint32_t bb = (uint32_t)(c & 1) * BUFB;
        if (c + 1 < NCH) ldg_chunk(c + 1);
        compute(bb, c >> 2);                          // chunks 0-3 -> set 0, 4-7 -> set 1
        if (c + 1 < NCH) {
            sts_chunk((uint32_t)((c + 1) & 1) * BUFB);
            __syncthreads();
        }
    }

    // epilogue: fp32 combine of the two fp16 sets -> g_partial[b][bid][co]
    float* op = g_partial + (size_t)blockIdx.x * CCO;
    const int rl = lid >> 2;
    const int cl = 2 * (lid & 3);
#pragma unroll
    for (int mt = 0; mt < 5; mt++) {
#pragma unroll
        for (int nt = 0; nt < 2; nt++) {
            float2 d0a = h2f2(acc[0][mt][nt][0]), d0b = h2f2(acc[1][mt][nt][0]);
            float2 d1a = h2f2(acc[0][mt][nt][1]), d1b = h2f2(acc[1][mt][nt][1]);
            float c0 = d0a.x + d0b.x;   // (co,   b)
            float c1 = d0a.y + d0b.y;   // (co,   b+1)
            float c2 = d1a.x + d1b.x;   // (co+8, b)
            float c3 = d1a.y + d1b.y;   // (co+8, b+1)
            int co = c0w + mt * 16 + rl;
            int b  = b0w + nt * 8 + cl;
            op[(size_t)b * (NSPLIT * CCO) + co]           = c0;
            op[(size_t)(b + 1) * (NSPLIT * CCO) + co]     = c1;
            op[(size_t)b * (NSPLIT * CCO) + co + 8]       = c2;
            op[(size_t)(b + 1) * (NSPLIT * CCO) + co + 8] = c3;
        }
    }
}

// ---------------------------------------------------------------------------
// Kernel 2: reduce partials + squash (R11 config, measured ~6.1us).
// ---------------------------------------------------------------------------
__global__ void __launch_bounds__(640, 1)
digitcaps_squash_kernel(float* __restrict__ out)
{
    __shared__ float4 red[16][40];
    __shared__ float  sv[CCO];

    const int b   = blockIdx.x;
    const int t   = threadIdx.x;
    const int ql  = t % 40;             // co quad (160/4)
    const int grp = t / 40;             // split group 0..15 (9 splits each)

    const float4* p = (const float4*)(g_partial + (size_t)b * (NSPLIT * CCO)) + ql;

    float4 v[9];
#pragma unroll
    for (int j = 0; j < 9; j++)
        v[j] = __ldg(p + (size_t)(grp * 9 + j) * (CCO / 4));

    float4 a = make_float4(0.f, 0.f, 0.f, 0.f);
#pragma unroll
    for (int j = 0; j < 9; j++) {
        a.x += v[j].x; a.y += v[j].y; a.z += v[j].z; a.w += v[j].w;
    }
    red[grp][ql] = a;
    __syncthreads();

    if (t < CCO) {
        const int qq = t >> 2, e = t & 3;
        float s = 0.f;
#pragma unroll
        for (int g = 0; g < 16; g++)
            s += ((const float*)&red[g][qq])[e];
        sv[t] = s * (1.0f / (float)RROUTE);
    }
    __syncthreads();

    if (t < CCO) {
        const int base = t & ~15;        // capsule start (16 o's)
        float sq = 0.f;
#pragma unroll
        for (int o = 0; o < 16; o++) {
            float vv = sv[base + o];
            sq += vv * vv;
        }
        float s = sv[t];
        out[(size_t)b * CCO + t] = s * sqrtf(sq) / (1.0f + sq);
    }
}

// ---------------------------------------------------------------------------
extern "C" void kernel_launch(void* const* d_in, const int* in_sizes, int n_in,
                              void* d_out, int out_size)
{
    const float* x = (const float*)d_in[0];   // [128, 4608, 8]
    const float* W = (const float*)d_in[1];   // [1, 4608, 10, 16, 8]
    float* out = (float*)d_out;               // [128, 10, 16]

    digitcaps_mma_kernel<<<NSPLIT, NTHREADS>>>(x, W);
    digitcaps_squash_kernel<<<RB, 640>>>(out);
}

// round 16
// speedup vs baseline: 1.2934x; 1.2934x over previous
#include <cuda_runtime.h>
#include <cuda_fp16.h>
#include <cstdint>

// Problem constants
#define RB      128         // batch  (GEMM N)
#define RROUTE  4608        // routes
#define CCO     160         // C*O    (GEMM M)
#define II      8

// K-split
#define NSPLIT  144         // CTAs
#define CHUNK_R 32          // routes per CTA (K=256)
#define CK_R    4           // routes per chunk
#define KCH     32          // k per chunk
#define NCH     8
#define NTHREADS 512

// smem rows (bytes), padded & 16B aligned, ldmatrix conflict-free
#define A_ROW   80          // W tile row: 40 fp16 (32 used)
#define B_ROW   272         // x tile row: 136 fp16 (128 used)
#define OFF_A   0
#define OFF_B   (CCO * A_ROW)            // 12800
#define BUFB    (OFF_B + KCH * B_ROW)    // 21504 per buffer
#define SMEM_SZ (2 * BUFB)               // 43008 static (double buffered, <48KB)

// partial results in fp16: [B][NSPLIT][CO]  (5.9MB — halves squash traffic)
__device__ __half g_partial_h[RB * NSPLIT * CCO];

// ---------------- helpers ----------------
__device__ __forceinline__ uint32_t smem_u32(const void* p) {
    uint32_t a;
    asm("{ .reg .u64 t; cvta.to.shared.u64 t, %1; cvt.u32.u64 %0, t; }" : "=r"(a) : "l"(p));
    return a;
}
__device__ __forceinline__ uint32_t packh(float e0, float e1) {
    uint32_t d;
    asm("cvt.rn.f16x2.f32 %0, %1, %2;" : "=r"(d) : "f"(e1), "f"(e0));
    return d;
}
__device__ __forceinline__ void sts32(uint32_t a, uint32_t r) {
    asm volatile("st.shared.b32 [%0], %1;" :: "r"(a), "r"(r) : "memory");
}
__device__ __forceinline__ void sts64(uint32_t a, uint32_t r0, uint32_t r1) {
    asm volatile("st.shared.v2.b32 [%0], {%1, %2};" :: "r"(a), "r"(r0), "r"(r1) : "memory");
}
__device__ __forceinline__ void ldmx4(uint32_t* r, uint32_t a) {
    asm volatile("ldmatrix.sync.aligned.m8n8.x4.shared.b16 {%0,%1,%2,%3}, [%4];"
                 : "=r"(r[0]), "=r"(r[1]), "=r"(r[2]), "=r"(r[3]) : "r"(a));
}
__device__ __forceinline__ void ldmx2t(uint32_t* r, uint32_t a) {
    asm volatile("ldmatrix.sync.aligned.m8n8.x2.trans.shared.b16 {%0,%1}, [%2];"
                 : "=r"(r[0]), "=r"(r[1]) : "r"(a));
}
__device__ __forceinline__ void mma16816(float* d, const uint32_t* a, const uint32_t* b) {
    asm volatile(
        "mma.sync.aligned.m16n8k16.row.col.f32.f16.f16.f32 "
        "{%0,%1,%2,%3}, {%4,%5,%6,%7}, {%8,%9}, {%0,%1,%2,%3};"
        : "+f"(d[0]), "+f"(d[1]), "+f"(d[2]), "+f"(d[3])
        : "r"(a[0]), "r"(a[1]), "r"(a[2]), "r"(a[3]), "r"(b[0]), "r"(b[1]));
}
__device__ __forceinline__ float f4elem(const float4& v, int j) {
    switch (j) { case 0: return v.x; case 1: return v.y; case 2: return v.z; default: return v.w; }
}

// ---------------------------------------------------------------------------
// Kernel 1: fp16 mma.sync partial GEMM (R9 config: fp32 acc, 1-deep prefetch).
// D[co][b] (per CTA) = sum_{k in 256-slab} W_k[co] * x_k[b]
// 16 warps: 2 (M=co, 80 each) x 8 (N=b, 16 each). Warp tile 80x16 = 5x2 tiles.
// Epilogue stores partials as fp16 (scattered STG.16; halves squash traffic).
// ---------------------------------------------------------------------------
__global__ void __launch_bounds__(NTHREADS, 1)
digitcaps_mma_kernel(const float* __restrict__ x, const float* __restrict__ W)
{
    __shared__ __align__(16) char smem_raw[SMEM_SZ];
    const uint32_t tiles = smem_u32(smem_raw);

    const int tid = threadIdx.x;
    const int lid = tid & 31;
    const int wid = tid >> 5;
    const int wm  = wid & 1;          // M-warp (co)
    const int wn  = wid >> 1;         // N-warp (b)
    const int c0w = wm * 80;
    const int b0w = wn * 16;
    const int r0  = blockIdx.x * CHUNK_R;

    // x conversion task: b-pair bp, quarter q (k = q*4 + j)
    const int bp = tid >> 3;
    const int q  = tid & 7;

    float acc[5][2][4];
#pragma unroll
    for (int mt = 0; mt < 5; mt++)
#pragma unroll
        for (int nt = 0; nt < 2; nt++)
#pragma unroll
            for (int e = 0; e < 4; e++) acc[mt][nt][e] = 0.f;

    float4 px0, px1, pw[3];

    auto ldg_chunk = [&](int ck) {
        const int rc0 = r0 + ck * CK_R;
        const float4* xb = (const float4*)(x + ((size_t)(2 * bp) * RROUTE + rc0) * II);
        px0 = __ldg(xb + q);
        px1 = __ldg(xb + (RROUTE * II / 4) + q);     // row b+1
#pragma unroll
        for (int t = 0; t < 3; t++) {
            int idx = tid + t * NTHREADS;
            if (idx < 1280) {
                int rr = idx / 320, rem = idx - rr * 320;
                int co = rem >> 1, ih = rem & 1;
                pw[t] = __ldg((const float4*)(W + ((size_t)(rc0 + rr) * CCO + co) * II) + ih);
            }
        }
    };

    auto sts_chunk = [&](uint32_t bb) {
        // x -> B tile [k][b] (transpose during store; fp16 pair (b, b+1) per word)
#pragma unroll
        for (int j = 0; j < 4; j++) {
            uint32_t h = packh(f4elem(px0, j), f4elem(px1, j));
            sts32(tiles + bb + OFF_B + (uint32_t)((q * 4 + j) * B_ROW + 4 * bp), h);
        }
        // W -> A tile [co][k] (natural, k-contiguous)
#pragma unroll
        for (int t = 0; t < 3; t++) {
            int idx = tid + t * NTHREADS;
            if (idx < 1280) {
                int rr = idx / 320, rem = idx - rr * 320;
                int co = rem >> 1, ih = rem & 1;
                uint32_t h0 = packh(pw[t].x, pw[t].y), h1 = packh(pw[t].z, pw[t].w);
                sts64(tiles + bb + OFF_A + (uint32_t)(co * A_ROW + rr * 16 + ih * 8), h0, h1);
            }
        }
    };

    auto compute = [&](uint32_t bb) {
#pragma unroll
        for (int ks = 0; ks < 2; ks++) {
            const uint32_t k0 = ks * 16;
            uint32_t bh[2][2];
            const uint32_t brow = k0 + (lid & 7) + ((lid >> 3) & 1) * 8;
#pragma unroll
            for (int nt = 0; nt < 2; nt++)
                ldmx2t(bh[nt], tiles + bb + OFF_B + brow * B_ROW + (uint32_t)(b0w + nt * 8) * 2);
#pragma unroll
            for (int mt = 0; mt < 5; mt++) {
                uint32_t ah[4];
                ldmx4(ah, tiles + bb + OFF_A
                          + (uint32_t)(c0w + mt * 16 + (lid & 15)) * A_ROW
                          + (k0 + (lid >> 4) * 8) * 2);
#pragma unroll
                for (int nt = 0; nt < 2; nt++)
                    mma16816(acc[mt][nt], ah, bh[nt]);
            }
        }
    };

    // pipeline: prefetch LDG(c+1) in regs over compute(c); STS into idle buffer
    ldg_chunk(0);
    sts_chunk(0);
    __syncthreads();
#pragma unroll 1
    for (int c = 0; c < NCH; c++) {
        const uint32_t bb = (uint32_t)(c & 1) * BUFB;
        if (c + 1 < NCH) ldg_chunk(c + 1);
        compute(bb);
        if (c + 1 < NCH) {
            sts_chunk((uint32_t)((c + 1) & 1) * BUFB);   // other buffer: no wait needed
            __syncthreads();
        }
    }

    // epilogue: acc -> fp16 g_partial_h[b][bid][co]
    const int s   = blockIdx.x;
    const int rl  = lid >> 2;
    const int cl  = 2 * (lid & 3);
#pragma unroll
    for (int mt = 0; mt < 5; mt++) {
#pragma unroll
        for (int nt = 0; nt < 2; nt++) {
            int co = c0w + mt * 16 + rl;
            int b  = b0w + nt * 8 + cl;
            size_t o0 = ((size_t)b * NSPLIT + s) * CCO + co;
            size_t o1 = ((size_t)(b + 1) * NSPLIT + s) * CCO + co;
            g_partial_h[o0]     = __float2half(acc[mt][nt][0]);
            g_partial_h[o1]     = __float2half(acc[mt][nt][1]);
            g_partial_h[o0 + 8] = __float2half(acc[mt][nt][2]);
            g_partial_h[o1 + 8] = __float2half(acc[mt][nt][3]);
        }
    }
}

// ---------------------------------------------------------------------------
// Kernel 2: reduce fp16 partials + squash. 5.9MB total read (halved).
// grid = 128 (b), block = 480: ql = co-octet (20 x 8 halfs), grp = split
// group (24 x 6 splits). Each thread: 6 uint4 loads (16B = 8 halfs each).
// ---------------------------------------------------------------------------
__global__ void __launch_bounds__(480, 1)
digitcaps_squash_kernel(float* __restrict__ out)
{
    __shared__ float red[24][CCO];
    __shared__ float sv[CCO];

    const int b   = blockIdx.x;
    const int t   = threadIdx.x;
    const int ql  = t % 20;             // co octet (160/8)
    const int grp = t / 20;             // split group 0..23 (6 splits each)

    const uint4* p = (const uint4*)(g_partial_h + (size_t)b * (NSPLIT * CCO)) + ql;

    // batch loads, then convert+accumulate in fp32
    uint4 v[6];
#pragma unroll
    for (int j = 0; j < 6; j++)
        v[j] = __ldg(p + (size_t)(grp * 6 + j) * (CCO / 8));

    float a[8];
#pragma unroll
    for (int e = 0; e < 8; e++) a[e] = 0.f;
#pragma unroll
    for (int j = 0; j < 6; j++) {
        const uint32_t* u = &v[j].x;
#pragma unroll
        for (int h = 0; h < 4; h++) {
            float2 f = __half22float2(*(const __half2*)&u[h]);
            a[2 * h]     += f.x;
            a[2 * h + 1] += f.y;
        }
    }
#pragma unroll
    for (int e = 0; e < 8; e++)
        red[grp][ql * 8 + e] = a[e];
    __syncthreads();

    if (t < CCO) {
        float s = 0.f;
#pragma unroll
        for (int g = 0; g < 24; g++)
            s += red[g][t];
        sv[t] = s * (1.0f / (float)RROUTE);
    }
    __syncthreads();

    if (t < CCO) {
        const int base = t & ~15;        // capsule start (16 o's)
        float sq = 0.f;
#pragma unroll
        for (int o = 0; o < 16; o++) {
            float vv = sv[base + o];
            sq += vv * vv;
        }
        float s = sv[t];
        out[(size_t)b * CCO + t] = s * sqrtf(sq) / (1.0f + sq);
    }
}

// ---------------------------------------------------------------------------
extern "C" void kernel_launch(void* const* d_in, const int* in_sizes, int n_in,
                              void* d_out, int out_size)
{
    const float* x = (const float*)d_in[0];   // [128, 4608, 8]
    const float* W = (const float*)d_in[1];   // [1, 4608, 10, 16, 8]
    float* out = (float*)d_out;               // [128, 10, 16]

    digitcaps_mma_kernel<<<NSPLIT, NTHREADS>>>(x, W);
    digitcaps_squash_kernel<<<RB, 480>>>(out);
}